// round 6
// baseline (speedup 1.0000x reference)
#include <cuda_runtime.h>
#include <cstdint>
#include <math.h>

// Problem dims (fixed for this dataset)
#define NATOMS 20000
#define NEDGES 250000
#define DE 512
#define DA 256
#define DR 16

#define INV_SQRT2 0.70710678118654752440f

typedef unsigned long long ull;

// K-permutation within each 32-element block: k' = (k%4)*8 + (k/4)%8
__host__ __device__ __forceinline__ int kperm(int k) {
    return (k & ~31) | ((k & 3) * 8) | ((k & 31) >> 2);
}

// ---------------- scratch (device globals; no allocs allowed) ----------------
__device__ int   g_counts[NATOMS];          // zero at load; scan re-zeroes each pass
__device__ int   g_offsets[NATOMS + 1];
__device__ int   g_cursor[NATOMS];
__device__ int   g_sorted[NEDGES];
__device__ float g_xbig[(size_t)NATOMS * DE];   // aggregated [A, De], tf32 + k-permuted
__device__ float g_xa[(size_t)NATOMS * DA];     // atom features (tf32, k-permuted)
__device__ float g_ya[(size_t)NATOMS * DA];     // MLP intermediate (tf32, k-permuted)
// transposed+tf32-rounded+k-permuted weights: W_in^T [256,512] then 3x(W1^T,W2^T) [256,256]
__device__ float g_wt[DA * DE + 6 * DA * DA];

// ---------------- helpers ----------------
__device__ __forceinline__ uint32_t smem_u32(const void* p) {
    uint32_t a;
    asm("{ .reg .u64 t; cvta.to.shared.u64 t, %1; cvt.u32.u64 %0, t; }" : "=r"(a) : "l"(p));
    return a;
}
__device__ __forceinline__ float tf32_rna(float x) {
    float y;
    asm("cvt.rna.tf32.f32 %0, %1;" : "=f"(y) : "f"(x));
    return y;
}
__device__ __forceinline__ float silu(float x) { return x / (1.0f + __expf(-x)); }

__device__ __forceinline__ ull pack2(float x, float y) {
    ull r; asm("mov.b64 %0, {%1, %2};" : "=l"(r) : "f"(x), "f"(y)); return r;
}
__device__ __forceinline__ void unpack2(ull v, float& x, float& y) {
    asm("mov.b64 {%0, %1}, %2;" : "=f"(x), "=f"(y) : "l"(v));
}
__device__ __forceinline__ ull fma2(ull a, ull b, ull c) {
    ull d; asm("fma.rn.f32x2 %0, %1, %2, %3;" : "=l"(d) : "l"(a), "l"(b), "l"(c)); return d;
}

__device__ __forceinline__ void cp_async16(uint32_t dst, const void* src, int pred) {
    asm volatile("cp.async.cg.shared.global [%0], [%1], 16, %2;"
                 :: "r"(dst), "l"(src), "r"(pred ? 16 : 0) : "memory");
}
__device__ __forceinline__ void cp_commit() {
    asm volatile("cp.async.commit_group;" ::: "memory");
}
__device__ __forceinline__ void cp_wait0() {
    asm volatile("cp.async.wait_group 0;" ::: "memory");
}
__device__ __forceinline__ void cp_wait1() {
    asm volatile("cp.async.wait_group 1;" ::: "memory");
}

// ---------------- counting sort of edges by atom ----------------
// hist also zero-fills g_xbig (needed by the boundary atomics in aggregate)
__global__ void hist_kernel(const int* __restrict__ idx, int E, int A) {
    int i = blockIdx.x * blockDim.x + threadIdx.x;
    if (i < E) atomicAdd(&g_counts[idx[i]], 1);
    int total4 = A * DE / 4;
    int nt = gridDim.x * blockDim.x;
    float4 z = make_float4(0.f, 0.f, 0.f, 0.f);
    for (int j = i; j < total4; j += nt)
        reinterpret_cast<float4*>(g_xbig)[j] = z;
}
__global__ void scan_kernel(int A, int E) {
    __shared__ int sums[1024];
    int tid = threadIdx.x;
    int per = (A + 1023) / 1024;
    int start = tid * per;
    int end = min(start + per, A);
    int s = 0;
    for (int i = start; i < end; i++) s += g_counts[i];
    sums[tid] = s;
    __syncthreads();
    for (int off = 1; off < 1024; off <<= 1) {
        int v = 0;
        if (tid >= off) v = sums[tid - off];
        __syncthreads();
        sums[tid] += v;
        __syncthreads();
    }
    int run = (tid == 0) ? 0 : sums[tid - 1];
    for (int i = start; i < end; i++) {
        g_offsets[i] = run;
        g_cursor[i]  = run;
        run += g_counts[i];
        g_counts[i] = 0;
    }
    if (tid == 0) g_offsets[A] = E;
}
__global__ void scatter_kernel(const int* __restrict__ idx, int E) {
    int i = blockIdx.x * blockDim.x + threadIdx.x;
    if (i < E) {
        int p = atomicAdd(&g_cursor[idx[i]], 1);
        g_sorted[p] = i;
    }
}

// ---------------- edge-parallel aggregation (packed f32x2 FMA) ----------------
// xbig[a, perm(d)] = rna( sum_{e in a} m[e,d] * (sum_r br[e,r] * W_rbf[r,d]) )
// Interior atoms: exclusive plain stores (rounded+permuted). Boundary atoms:
// atomicAdd of raw partials onto pre-zeroed xbig (implicit tf32 truncation later).
#define AGG_TILE 64
#define AGG_BLOCKS 740

__global__ __launch_bounds__(128, 4)
void aggregate_kernel(const float* __restrict__ m,
                      const float* __restrict__ br,
                      const float* __restrict__ Wrbf,
                      const int* __restrict__ idx, int E) {
    __shared__ float s_br[AGG_TILE][16];
    __shared__ int   s_e[AGG_TILE];
    __shared__ int   s_atom[AGG_TILE];

    const int tid = threadIdx.x;
    const int c0 = tid * 4;
    ull w01[DR], w23[DR];
#pragma unroll
    for (int r = 0; r < DR; r++) {
        float4 wv = *reinterpret_cast<const float4*>(Wrbf + (size_t)r * DE + c0);
        w01[r] = pack2(wv.x, wv.y);
        w23[r] = pack2(wv.z, wv.w);
    }
    const int pbase = (tid >> 3) * 32 + (tid & 7);   // permuted column base

    const int epb = (E + gridDim.x - 1) / gridDim.x;
    const int j0 = blockIdx.x * epb;
    const int j1 = min(j0 + epb, E);
    if (j0 >= j1) return;

    const int first_a = idx[g_sorted[j0]];
    const int last_a  = idx[g_sorted[j1 - 1]];

    ull acc01 = pack2(0.f, 0.f), acc23 = acc01;
    int cur_atom = -1;

    auto flush = [&](int a) {
        float x0, x1, x2, x3;
        unpack2(acc01, x0, x1);
        unpack2(acc23, x2, x3);
        float* p = g_xbig + (size_t)a * DE;
        if (a != first_a && a != last_a) {
            p[pbase]      = tf32_rna(x0);
            p[pbase + 8]  = tf32_rna(x1);
            p[pbase + 16] = tf32_rna(x2);
            p[pbase + 24] = tf32_rna(x3);
        } else {
            atomicAdd(p + pbase,      x0);
            atomicAdd(p + pbase + 8,  x1);
            atomicAdd(p + pbase + 16, x2);
            atomicAdd(p + pbase + 24, x3);
        }
    };

    for (int t0 = j0; t0 < j1; t0 += AGG_TILE) {
        const int n = min(AGG_TILE, j1 - t0);
        __syncthreads();
        {   // stage basis rows + atom ids: 2 threads per edge
            int el = tid >> 1;
            int half = tid & 1;
            if (el < n) {
                int e = g_sorted[t0 + el];
                if (half == 0) { s_e[el] = e; s_atom[el] = idx[e]; }
                const float* bp = br + (size_t)e * DR + half * 8;
                *reinterpret_cast<float4*>(&s_br[el][half * 8]) =
                    *reinterpret_cast<const float4*>(bp);
                *reinterpret_cast<float4*>(&s_br[el][half * 8 + 4]) =
                    *reinterpret_cast<const float4*>(bp + 4);
            }
        }
        __syncthreads();

        // 2-ahead m prefetch
        float4 mv  = *reinterpret_cast<const float4*>(m + (size_t)s_e[0] * DE + c0);
        float4 mv1 = mv;
        if (n > 1) mv1 = *reinterpret_cast<const float4*>(m + (size_t)s_e[1] * DE + c0);

        for (int i = 0; i < n; i++) {
            float4 mv2 = mv1;
            if (i + 2 < n)
                mv2 = *reinterpret_cast<const float4*>(m + (size_t)s_e[i + 2] * DE + c0);

            int a = s_atom[i];
            if (a != cur_atom) {
                if (cur_atom >= 0) flush(cur_atom);
                cur_atom = a;
                acc01 = pack2(0.f, 0.f);
                acc23 = acc01;
            }
            ull bs01 = pack2(0.f, 0.f), bs23 = bs01;
            const float4* bq = reinterpret_cast<const float4*>(s_br[i]);
#pragma unroll
            for (int q = 0; q < 4; q++) {
                float4 bb = bq[q];   // broadcast LDS.128
                ull b0 = pack2(bb.x, bb.x);
                ull b1 = pack2(bb.y, bb.y);
                ull b2 = pack2(bb.z, bb.z);
                ull b3 = pack2(bb.w, bb.w);
                bs01 = fma2(b0, w01[q * 4 + 0], bs01);
                bs23 = fma2(b0, w23[q * 4 + 0], bs23);
                bs01 = fma2(b1, w01[q * 4 + 1], bs01);
                bs23 = fma2(b1, w23[q * 4 + 1], bs23);
                bs01 = fma2(b2, w01[q * 4 + 2], bs01);
                bs23 = fma2(b2, w23[q * 4 + 2], bs23);
                bs01 = fma2(b3, w01[q * 4 + 3], bs01);
                bs23 = fma2(b3, w23[q * 4 + 3], bs23);
            }
            acc01 = fma2(pack2(mv.x, mv.y), bs01, acc01);
            acc23 = fma2(pack2(mv.z, mv.w), bs23, acc23);
            mv = mv1;
            mv1 = mv2;
        }
    }
    if (cur_atom >= 0) flush(cur_atom);
}

// ---------------- all-weights transpose + tf32 round + k-permute ----------------
__global__ void transpose_all_kernel(const float* __restrict__ Win,
                                     const float* __restrict__ W1,
                                     const float* __restrict__ W2,
                                     float* __restrict__ wt, int nh) {
    int total = DE * DA + 2 * nh * DA * DA;
    for (int i = blockIdx.x * blockDim.x + threadIdx.x; i < total;
         i += gridDim.x * blockDim.x) {
        const float* src;
        float* dst;
        int K, rem;
        if (i < DE * DA) {
            src = Win; dst = wt; K = DE; rem = i;
        } else {
            int j = i - DE * DA;
            int t = j / (DA * DA);
            rem = j % (DA * DA);
            src = ((t & 1) == 0 ? W1 : W2) + (size_t)(t >> 1) * DA * DA;
            dst = wt + DE * DA + (size_t)t * DA * DA;
            K = DA;
        }
        int k = rem / DA, n = rem % DA;
        dst[(size_t)n * K + kperm(k)] = tf32_rna(src[rem]);
    }
}

// ---------------- mma.sync tf32 GEMM, tile 64x128, 3-stage cp.async pipeline ----------------
#define BK 32
#define LDS_K 36
#define A_FLOATS (64 * LDS_K)
#define B_FLOATS (128 * LDS_K)
#define BUF_FLOATS (A_FLOATS + B_FLOATS)
#define STAGES 3
#define GEMM_SMEM (STAGES * BUF_FLOATS * 4)   // 82944 B

__global__ __launch_bounds__(128, 2)
void gemm_mma_kernel(const float* __restrict__ Ain, const float* __restrict__ Wt,
                     const float* __restrict__ res, float* __restrict__ out,
                     int M, int K, int mode, int perm_out) {
    extern __shared__ float smem[];
    const uint32_t sbase = smem_u32(smem);

    const int tid = threadIdx.x;
    const int lane = tid & 31;
    const int wid = tid >> 5;
    const int warp_m = wid & 1;
    const int warp_n = wid >> 1;
    const int bm = blockIdx.x * 64;
    const int bn = blockIdx.y * 128;
    const int r = lane >> 2;
    const int c = lane & 3;

    const int a_row = tid >> 1;
    const int a_col = (tid & 1) * 16;
    const bool a_valid = (bm + a_row) < M;
    const float* gA = Ain + (size_t)(bm + a_row) * K + a_col;
    const float* gB = Wt + (size_t)(bn + tid) * K;

    uint32_t sA_dst[STAGES], sB_dst[STAGES];
#pragma unroll
    for (int s = 0; s < STAGES; s++) {
        sA_dst[s] = sbase + (s * BUF_FLOATS + a_row * LDS_K + a_col) * 4;
        sB_dst[s] = sbase + (s * BUF_FLOATS + A_FLOATS + tid * LDS_K) * 4;
    }

    auto prefetch = [&](int kt, int stg) {
        int k0 = kt * BK;
#pragma unroll
        for (int j = 0; j < 4; j++)
            cp_async16(sA_dst[stg] + j * 16, gA + k0 + j * 4, a_valid);
#pragma unroll
        for (int j = 0; j < 8; j++)
            cp_async16(sB_dst[stg] + j * 16, gB + k0 + j * 4, 1);
        cp_commit();
    };

    float acc[2][8][4];
#pragma unroll
    for (int mt = 0; mt < 2; mt++)
#pragma unroll
        for (int nt = 0; nt < 8; nt++)
#pragma unroll
            for (int v = 0; v < 4; v++) acc[mt][nt][v] = 0.f;

    const int nk = K / BK;
    prefetch(0, 0);
    prefetch(1, 1);

    int stg = 0;
    for (int kt = 0; kt < nk; kt++) {
        if (kt + 1 < nk) cp_wait1();
        else             cp_wait0();
        __syncthreads();
        if (kt + 2 < nk) prefetch(kt + 2, (stg + 2) % STAGES);

        const float* wA = smem + stg * BUF_FLOATS + (warp_m * 32) * LDS_K;
        const float* wB = smem + stg * BUF_FLOATS + A_FLOATS + (warp_n * 64) * LDS_K;
#pragma unroll
        for (int half = 0; half < 2; half++) {
            float av[2][2][4];
#pragma unroll
            for (int mt = 0; mt < 2; mt++) {
                *reinterpret_cast<float4*>(av[mt][0]) =
                    *reinterpret_cast<const float4*>(wA + (mt * 16 + r) * LDS_K + c * 8 + half * 4);
                *reinterpret_cast<float4*>(av[mt][1]) =
                    *reinterpret_cast<const float4*>(wA + (mt * 16 + 8 + r) * LDS_K + c * 8 + half * 4);
            }
            float bv[8][4];
#pragma unroll
            for (int nt = 0; nt < 8; nt++)
                *reinterpret_cast<float4*>(bv[nt]) =
                    *reinterpret_cast<const float4*>(wB + (nt * 8 + r) * LDS_K + c * 8 + half * 4);
#pragma unroll
            for (int s = 0; s < 2; s++) {
#pragma unroll
                for (int mt = 0; mt < 2; mt++)
#pragma unroll
                    for (int nt = 0; nt < 8; nt++) {
                        float* d = acc[mt][nt];
                        asm volatile(
                            "mma.sync.aligned.m16n8k8.row.col.f32.tf32.tf32.f32 "
                            "{%0,%1,%2,%3}, {%4,%5,%6,%7}, {%8,%9}, {%0,%1,%2,%3};"
                            : "+f"(d[0]), "+f"(d[1]), "+f"(d[2]), "+f"(d[3])
                            : "r"(__float_as_uint(av[mt][0][2 * s])),
                              "r"(__float_as_uint(av[mt][1][2 * s])),
                              "r"(__float_as_uint(av[mt][0][2 * s + 1])),
                              "r"(__float_as_uint(av[mt][1][2 * s + 1])),
                              "r"(__float_as_uint(bv[nt][2 * s])),
                              "r"(__float_as_uint(bv[nt][2 * s + 1])));
                    }
            }
        }
        __syncthreads();
        stg = (stg + 1) % STAGES;
    }

#pragma unroll
    for (int mt = 0; mt < 2; mt++) {
#pragma unroll
        for (int half = 0; half < 2; half++) {
            int row = bm + warp_m * 32 + mt * 16 + half * 8 + r;
            if (row >= M) continue;
            float* op = out + (size_t)row * DA;
            const float* rp = (mode == 1) ? res + (size_t)row * DA : nullptr;
#pragma unroll
            for (int nt = 0; nt < 8; nt++) {
                int col = bn + warp_n * 64 + nt * 8 + c * 2;
                int pc = kperm(col);
                float v0 = silu(acc[mt][nt][half * 2 + 0]);
                float v1 = silu(acc[mt][nt][half * 2 + 1]);
                if (mode == 1) {
                    v0 = (rp[pc] + v0) * INV_SQRT2;
                    v1 = (rp[pc + 8] + v1) * INV_SQRT2;
                }
                if (perm_out) {
                    op[pc]     = tf32_rna(v0);
                    op[pc + 8] = tf32_rna(v1);
                } else {
                    *reinterpret_cast<float2*>(op + col) = make_float2(v0, v1);
                }
            }
        }
    }
}

// ---------------- launch ----------------
extern "C" void kernel_launch(void* const* d_in, const int* in_sizes, int n_in,
                              void* d_out, int out_size) {
    // inputs: 0:h (unused), 1:m, 2:basis_rad, 3:idx_atom, 4:W_rbf, 5:W_in, 6:res_W1, 7:res_W2
    const float* m    = (const float*)d_in[1];
    const float* br   = (const float*)d_in[2];
    const int*   idx  = (const int*)d_in[3];
    const float* Wrbf = (const float*)d_in[4];
    const float* Win  = (const float*)d_in[5];
    const float* W1   = (const float*)d_in[6];
    const float* W2   = (const float*)d_in[7];
    float* out = (float*)d_out;

    int A  = in_sizes[0] / DA;           // 20000
    int E  = in_sizes[1] / DE;           // 250000
    int nh = in_sizes[6] / (DA * DA);    // 3
    if (A > NATOMS) A = NATOMS;
    if (E > NEDGES) E = NEDGES;

    float *xbig, *xa, *ya, *wt;
    cudaGetSymbolAddress((void**)&xbig, g_xbig);
    cudaGetSymbolAddress((void**)&xa, g_xa);
    cudaGetSymbolAddress((void**)&ya, g_ya);
    cudaGetSymbolAddress((void**)&wt, g_wt);

    static bool attr_set = false;
    if (!attr_set) {
        cudaFuncSetAttribute(gemm_mma_kernel,
                             cudaFuncAttributeMaxDynamicSharedMemorySize, GEMM_SMEM);
        attr_set = true;
    }

    // counting sort (hist also zero-fills xbig for the aggregation atomics)
    hist_kernel<<<(E + 255) / 256, 256>>>(idx, E, A);
    scan_kernel<<<1, 1024>>>(A, E);
    scatter_kernel<<<(E + 255) / 256, 256>>>(idx, E);

    // edge-parallel aggregation (4th launch -> ncu capture slot)
    aggregate_kernel<<<AGG_BLOCKS, 128>>>(m, br, Wrbf, idx, E);

    // all weight transposes in one launch
    transpose_all_kernel<<<592, 256>>>(Win, W1, W2, wt, nh);

    float* wt0 = wt;  // W_in^T [256, 512]
    dim3 grid((A + 63) / 64, DA / 128);
    // x = silu(xbig @ W_in)
    gemm_mma_kernel<<<grid, 128, GEMM_SMEM>>>(xbig, wt0, nullptr, xa, A, DE, 0, 1);

    // residual layers
    for (int i = 0; i < nh; i++) {
        float* w1t = wt + DA * DE + (size_t)(2 * i) * DA * DA;
        float* w2t = wt + DA * DE + (size_t)(2 * i + 1) * DA * DA;
        gemm_mma_kernel<<<grid, 128, GEMM_SMEM>>>(xa, w1t, nullptr, ya, A, DA, 0, 1);
        float* dst = (i == nh - 1) ? out : xa;
        int po = (i == nh - 1) ? 0 : 1;
        gemm_mma_kernel<<<grid, 128, GEMM_SMEM>>>(ya, w2t, xa, dst, A, DA, 1, po);
    }
}

// round 7
// speedup vs baseline: 1.3094x; 1.3094x over previous
#include <cuda_runtime.h>
#include <cstdint>
#include <math.h>

// Problem dims (fixed for this dataset)
#define NATOMS 20000
#define NEDGES 250000
#define DE 512
#define DA 256
#define DR 16

#define INV_SQRT2 0.70710678118654752440f

// K-permutation within each 32-element block: k' = (k%4)*8 + (k/4)%8
__host__ __device__ __forceinline__ int kperm(int k) {
    return (k & ~31) | ((k & 3) * 8) | ((k & 31) >> 2);
}

// ---------------- scratch (device globals; no allocs allowed) ----------------
__device__ int   g_counts[NATOMS];          // zero at load; scan re-zeroes each pass
__device__ int   g_offsets[NATOMS + 1];
__device__ int   g_cursor[NATOMS];
__device__ int   g_sorted[NEDGES];
__device__ float g_xbig[(size_t)NATOMS * DE];   // aggregated [A, De], tf32 + k-permuted
__device__ float g_xa[(size_t)NATOMS * DA];     // atom features (tf32, k-permuted)
__device__ float g_ya[(size_t)NATOMS * DA];     // MLP intermediate (tf32, k-permuted)
// transposed+tf32-rounded+k-permuted weights: W_in^T [256,512] then 3x(W1^T,W2^T) [256,256]
__device__ float g_wt[DA * DE + 6 * DA * DA];

// ---------------- helpers ----------------
__device__ __forceinline__ uint32_t smem_u32(const void* p) {
    uint32_t a;
    asm("{ .reg .u64 t; cvta.to.shared.u64 t, %1; cvt.u32.u64 %0, t; }" : "=r"(a) : "l"(p));
    return a;
}
__device__ __forceinline__ float tf32_rna(float x) {
    float y;
    asm("cvt.rna.tf32.f32 %0, %1;" : "=f"(y) : "f"(x));
    return y;
}
__device__ __forceinline__ float silu(float x) { return x / (1.0f + __expf(-x)); }

__device__ __forceinline__ void cp_async16(uint32_t dst, const void* src, int pred) {
    asm volatile("cp.async.cg.shared.global [%0], [%1], 16, %2;"
                 :: "r"(dst), "l"(src), "r"(pred ? 16 : 0) : "memory");
}
__device__ __forceinline__ void cp_commit() {
    asm volatile("cp.async.commit_group;" ::: "memory");
}
__device__ __forceinline__ void cp_wait0() {
    asm volatile("cp.async.wait_group 0;" ::: "memory");
}

// ---------------- counting sort of edges by atom ----------------
// hist also zero-fills g_xbig (needed by the boundary atomics in aggregate)
__global__ void hist_kernel(const int* __restrict__ idx, int E, int A) {
    int i = blockIdx.x * blockDim.x + threadIdx.x;
    if (i < E) atomicAdd(&g_counts[idx[i]], 1);
    int total4 = A * DE / 4;
    int nt = gridDim.x * blockDim.x;
    float4 z = make_float4(0.f, 0.f, 0.f, 0.f);
    for (int j = i; j < total4; j += nt)
        reinterpret_cast<float4*>(g_xbig)[j] = z;
}
__global__ void scan_kernel(int A, int E) {
    __shared__ int sums[1024];
    int tid = threadIdx.x;
    int per = (A + 1023) / 1024;
    int start = tid * per;
    int end = min(start + per, A);
    int s = 0;
    for (int i = start; i < end; i++) s += g_counts[i];
    sums[tid] = s;
    __syncthreads();
    for (int off = 1; off < 1024; off <<= 1) {
        int v = 0;
        if (tid >= off) v = sums[tid - off];
        __syncthreads();
        sums[tid] += v;
        __syncthreads();
    }
    int run = (tid == 0) ? 0 : sums[tid - 1];
    for (int i = start; i < end; i++) {
        g_offsets[i] = run;
        g_cursor[i]  = run;
        run += g_counts[i];
        g_counts[i] = 0;
    }
    if (tid == 0) g_offsets[A] = E;
}
__global__ void scatter_kernel(const int* __restrict__ idx, int E) {
    int i = blockIdx.x * blockDim.x + threadIdx.x;
    if (i < E) {
        int p = atomicAdd(&g_cursor[idx[i]], 1);
        g_sorted[p] = i;
    }
}

// ---------------- edge-parallel aggregation (256 thr, 2 cols/thread) ----------------
// xbig[a, perm(d)] = rna( sum_{e in a} m[e,d] * (sum_r br[e,r] * W_rbf[r,d]) )
// Interior atoms: exclusive plain stores (rounded+permuted). Boundary atoms:
// atomicAdd of raw partials onto pre-zeroed xbig (truncated to tf32 by the GEMM).
#define AGG_TILE 64
#define AGG_BLOCKS 592

__global__ __launch_bounds__(256, 4)
void aggregate_kernel(const float* __restrict__ m,
                      const float* __restrict__ br,
                      const float* __restrict__ Wrbf,
                      const int* __restrict__ idx, int E) {
    __shared__ float s_br[AGG_TILE][16];
    __shared__ int   s_e[AGG_TILE];
    __shared__ int   s_atom[AGG_TILE];

    const int tid = threadIdx.x;
    const int c0 = tid * 2;                 // this thread's 2 logical columns
    float2 w[DR];
#pragma unroll
    for (int r = 0; r < DR; r++)
        w[r] = *reinterpret_cast<const float2*>(Wrbf + (size_t)r * DE + c0);

    // permuted store positions for logical columns c0 (even) and c0+1 (odd)
    const int p0 = kperm(c0);               // position of c0;  c0+1 -> p0 + 8
    const int epb = (E + gridDim.x - 1) / gridDim.x;
    const int j0 = blockIdx.x * epb;
    const int j1 = min(j0 + epb, E);
    if (j0 >= j1) return;

    const int first_a = idx[g_sorted[j0]];
    const int last_a  = idx[g_sorted[j1 - 1]];

    float2 acc = make_float2(0.f, 0.f);
    int cur_atom = -1;

    auto flush = [&](int a) {
        float* p = g_xbig + (size_t)a * DE;
        if (a != first_a && a != last_a) {
            p[p0]     = tf32_rna(acc.x);
            p[p0 + 8] = tf32_rna(acc.y);
        } else {
            atomicAdd(p + p0,     acc.x);
            atomicAdd(p + p0 + 8, acc.y);
        }
    };

    for (int t0 = j0; t0 < j1; t0 += AGG_TILE) {
        const int n = min(AGG_TILE, j1 - t0);
        __syncthreads();
        {   // stage basis rows + atom ids: 4 threads per edge, 1 float4 each
            int el = tid >> 2;
            int q = tid & 3;
            if (el < n) {
                int e = g_sorted[t0 + el];
                if (q == 0) { s_e[el] = e; s_atom[el] = idx[e]; }
                *reinterpret_cast<float4*>(&s_br[el][q * 4]) =
                    *reinterpret_cast<const float4*>(br + (size_t)e * DR + q * 4);
            }
        }
        __syncthreads();

        float2 mv = *reinterpret_cast<const float2*>(m + (size_t)s_e[0] * DE + c0);
        for (int i = 0; i < n; i++) {
            float2 mnext = mv;
            if (i + 1 < n)
                mnext = *reinterpret_cast<const float2*>(m + (size_t)s_e[i + 1] * DE + c0);

            int a = s_atom[i];
            if (a != cur_atom) {
                if (cur_atom >= 0) flush(cur_atom);
                cur_atom = a;
                acc = make_float2(0.f, 0.f);
            }
            float2 bs = make_float2(0.f, 0.f);
            const float4* bq = reinterpret_cast<const float4*>(s_br[i]);
#pragma unroll
            for (int q = 0; q < 4; q++) {
                float4 bb = bq[q];   // broadcast LDS.128
                float2 w0 = w[q * 4 + 0], w1 = w[q * 4 + 1];
                float2 w2 = w[q * 4 + 2], w3 = w[q * 4 + 3];
                bs.x = fmaf(bb.x, w0.x, bs.x); bs.y = fmaf(bb.x, w0.y, bs.y);
                bs.x = fmaf(bb.y, w1.x, bs.x); bs.y = fmaf(bb.y, w1.y, bs.y);
                bs.x = fmaf(bb.z, w2.x, bs.x); bs.y = fmaf(bb.z, w2.y, bs.y);
                bs.x = fmaf(bb.w, w3.x, bs.x); bs.y = fmaf(bb.w, w3.y, bs.y);
            }
            acc.x = fmaf(mv.x, bs.x, acc.x);
            acc.y = fmaf(mv.y, bs.y, acc.y);
            mv = mnext;
        }
    }
    if (cur_atom >= 0) flush(cur_atom);
}

// ---------------- all-weights transpose + tf32 round + k-permute ----------------
__global__ void transpose_all_kernel(const float* __restrict__ Win,
                                     const float* __restrict__ W1,
                                     const float* __restrict__ W2,
                                     float* __restrict__ wt, int nh) {
    int total = DE * DA + 2 * nh * DA * DA;
    for (int i = blockIdx.x * blockDim.x + threadIdx.x; i < total;
         i += gridDim.x * blockDim.x) {
        const float* src;
        float* dst;
        int K, rem;
        if (i < DE * DA) {
            src = Win; dst = wt; K = DE; rem = i;
        } else {
            int j = i - DE * DA;
            int t = j / (DA * DA);
            rem = j % (DA * DA);
            src = ((t & 1) == 0 ? W1 : W2) + (size_t)(t >> 1) * DA * DA;
            dst = wt + DE * DA + (size_t)t * DA * DA;
            K = DA;
        }
        int k = rem / DA, n = rem % DA;
        dst[(size_t)n * K + kperm(k)] = tf32_rna(src[rem]);
    }
}

// ---------------- mma.sync tf32 GEMM, tile 64x128, 2-stage cp.async (R5 config) ----------------
#define BK 32
#define LDS_K 36
#define A_FLOATS (64 * LDS_K)
#define B_FLOATS (128 * LDS_K)
#define BUF_FLOATS (A_FLOATS + B_FLOATS)
#define GEMM_SMEM (2 * BUF_FLOATS * 4)   // 55296 B

__global__ __launch_bounds__(128, 3)
void gemm_mma_kernel(const float* __restrict__ Ain, const float* __restrict__ Wt,
                     const float* __restrict__ res, float* __restrict__ out,
                     int M, int K, int mode, int perm_out) {
    extern __shared__ float smem[];
    float* sA[2] = {smem, smem + BUF_FLOATS};
    float* sB[2] = {smem + A_FLOATS, smem + BUF_FLOATS + A_FLOATS};
    const uint32_t sbase = smem_u32(smem);

    const int tid = threadIdx.x;
    const int lane = tid & 31;
    const int wid = tid >> 5;
    const int warp_m = wid & 1;
    const int warp_n = wid >> 1;
    const int bm = blockIdx.x * 64;
    const int bn = blockIdx.y * 128;
    const int r = lane >> 2;
    const int c = lane & 3;

    const int a_row = tid >> 1;
    const int a_col = (tid & 1) * 16;
    const bool a_valid = (bm + a_row) < M;
    const float* gA = Ain + (size_t)(bm + a_row) * K + a_col;
    const float* gB = Wt + (size_t)(bn + tid) * K;

    const uint32_t sA_dst[2] = {sbase + (0 * BUF_FLOATS + a_row * LDS_K + a_col) * 4,
                                sbase + (1 * BUF_FLOATS + a_row * LDS_K + a_col) * 4};
    const uint32_t sB_dst[2] = {sbase + (0 * BUF_FLOATS + A_FLOATS + tid * LDS_K) * 4,
                                sbase + (1 * BUF_FLOATS + A_FLOATS + tid * LDS_K) * 4};

    auto prefetch = [&](int kt, int buf) {
        int k0 = kt * BK;
#pragma unroll
        for (int j = 0; j < 4; j++)
            cp_async16(sA_dst[buf] + j * 16, gA + k0 + j * 4, a_valid);
#pragma unroll
        for (int j = 0; j < 8; j++)
            cp_async16(sB_dst[buf] + j * 16, gB + k0 + j * 4, 1);
        cp_commit();
    };

    float acc[2][8][4];
#pragma unroll
    for (int mt = 0; mt < 2; mt++)
#pragma unroll
        for (int nt = 0; nt < 8; nt++)
#pragma unroll
            for (int v = 0; v < 4; v++) acc[mt][nt][v] = 0.f;

    const int nk = K / BK;
    prefetch(0, 0);
    int buf = 0;
    for (int kt = 0; kt < nk; kt++) {
        cp_wait0();
        __syncthreads();
        if (kt + 1 < nk) prefetch(kt + 1, buf ^ 1);

        const float* wA = sA[buf] + (warp_m * 32) * LDS_K;
        const float* wB = sB[buf] + (warp_n * 64) * LDS_K;
#pragma unroll
        for (int half = 0; half < 2; half++) {
            float av[2][2][4];
#pragma unroll
            for (int mt = 0; mt < 2; mt++) {
                *reinterpret_cast<float4*>(av[mt][0]) =
                    *reinterpret_cast<const float4*>(wA + (mt * 16 + r) * LDS_K + c * 8 + half * 4);
                *reinterpret_cast<float4*>(av[mt][1]) =
                    *reinterpret_cast<const float4*>(wA + (mt * 16 + 8 + r) * LDS_K + c * 8 + half * 4);
            }
            float bv[8][4];
#pragma unroll
            for (int nt = 0; nt < 8; nt++)
                *reinterpret_cast<float4*>(bv[nt]) =
                    *reinterpret_cast<const float4*>(wB + (nt * 8 + r) * LDS_K + c * 8 + half * 4);
#pragma unroll
            for (int s = 0; s < 2; s++) {
#pragma unroll
                for (int mt = 0; mt < 2; mt++)
#pragma unroll
                    for (int nt = 0; nt < 8; nt++) {
                        float* d = acc[mt][nt];
                        asm volatile(
                            "mma.sync.aligned.m16n8k8.row.col.f32.tf32.tf32.f32 "
                            "{%0,%1,%2,%3}, {%4,%5,%6,%7}, {%8,%9}, {%0,%1,%2,%3};"
                            : "+f"(d[0]), "+f"(d[1]), "+f"(d[2]), "+f"(d[3])
                            : "r"(__float_as_uint(av[mt][0][2 * s])),
                              "r"(__float_as_uint(av[mt][1][2 * s])),
                              "r"(__float_as_uint(av[mt][0][2 * s + 1])),
                              "r"(__float_as_uint(av[mt][1][2 * s + 1])),
                              "r"(__float_as_uint(bv[nt][2 * s])),
                              "r"(__float_as_uint(bv[nt][2 * s + 1])));
                    }
            }
        }
        __syncthreads();
        buf ^= 1;
    }

#pragma unroll
    for (int mt = 0; mt < 2; mt++) {
#pragma unroll
        for (int half = 0; half < 2; half++) {
            int row = bm + warp_m * 32 + mt * 16 + half * 8 + r;
            if (row >= M) continue;
            float* op = out + (size_t)row * DA;
            const float* rp = (mode == 1) ? res + (size_t)row * DA : nullptr;
#pragma unroll
            for (int nt = 0; nt < 8; nt++) {
                int col = bn + warp_n * 64 + nt * 8 + c * 2;
                int pc = kperm(col);
                float v0 = silu(acc[mt][nt][half * 2 + 0]);
                float v1 = silu(acc[mt][nt][half * 2 + 1]);
                if (mode == 1) {
                    v0 = (rp[pc] + v0) * INV_SQRT2;
                    v1 = (rp[pc + 8] + v1) * INV_SQRT2;
                }
                if (perm_out) {
                    op[pc]     = tf32_rna(v0);
                    op[pc + 8] = tf32_rna(v1);
                } else {
                    *reinterpret_cast<float2*>(op + col) = make_float2(v0, v1);
                }
            }
        }
    }
}

// ---------------- launch ----------------
extern "C" void kernel_launch(void* const* d_in, const int* in_sizes, int n_in,
                              void* d_out, int out_size) {
    // inputs: 0:h (unused), 1:m, 2:basis_rad, 3:idx_atom, 4:W_rbf, 5:W_in, 6:res_W1, 7:res_W2
    const float* m    = (const float*)d_in[1];
    const float* br   = (const float*)d_in[2];
    const int*   idx  = (const int*)d_in[3];
    const float* Wrbf = (const float*)d_in[4];
    const float* Win  = (const float*)d_in[5];
    const float* W1   = (const float*)d_in[6];
    const float* W2   = (const float*)d_in[7];
    float* out = (float*)d_out;

    int A  = in_sizes[0] / DA;           // 20000
    int E  = in_sizes[1] / DE;           // 250000
    int nh = in_sizes[6] / (DA * DA);    // 3
    if (A > NATOMS) A = NATOMS;
    if (E > NEDGES) E = NEDGES;

    float *xbig, *xa, *ya, *wt;
    cudaGetSymbolAddress((void**)&xbig, g_xbig);
    cudaGetSymbolAddress((void**)&xa, g_xa);
    cudaGetSymbolAddress((void**)&ya, g_ya);
    cudaGetSymbolAddress((void**)&wt, g_wt);

    static bool attr_set = false;
    if (!attr_set) {
        cudaFuncSetAttribute(gemm_mma_kernel,
                             cudaFuncAttributeMaxDynamicSharedMemorySize, GEMM_SMEM);
        attr_set = true;
    }

    // counting sort (hist also zero-fills xbig for the aggregation atomics)
    hist_kernel<<<(E + 255) / 256, 256>>>(idx, E, A);
    scan_kernel<<<1, 1024>>>(A, E);
    scatter_kernel<<<(E + 255) / 256, 256>>>(idx, E);

    // edge-parallel aggregation (4th launch -> ncu capture slot)
    aggregate_kernel<<<AGG_BLOCKS, 256>>>(m, br, Wrbf, idx, E);

    // all weight transposes in one launch
    transpose_all_kernel<<<592, 256>>>(Win, W1, W2, wt, nh);

    float* wt0 = wt;  // W_in^T [256, 512]
    dim3 grid((A + 63) / 64, DA / 128);
    // x = silu(xbig @ W_in)
    gemm_mma_kernel<<<grid, 128, GEMM_SMEM>>>(xbig, wt0, nullptr, xa, A, DE, 0, 1);

    // residual layers
    for (int i = 0; i < nh; i++) {
        float* w1t = wt + DA * DE + (size_t)(2 * i) * DA * DA;
        float* w2t = wt + DA * DE + (size_t)(2 * i + 1) * DA * DA;
        gemm_mma_kernel<<<grid, 128, GEMM_SMEM>>>(xa, w1t, nullptr, ya, A, DA, 0, 1);
        float* dst = (i == nh - 1) ? out : xa;
        int po = (i == nh - 1) ? 0 : 1;
        gemm_mma_kernel<<<grid, 128, GEMM_SMEM>>>(ya, w2t, xa, dst, A, DA, 1, po);
    }
}